// round 1
// baseline (speedup 1.0000x reference)
#include <cuda_runtime.h>
#include <math.h>

// ---------------- problem constants ----------------
#define T_FR   8
#define N_TOK  257
#define HW     16
#define BATCH  8
#define D_MOD  768
#define DH     192
#define HEADS  4
#define HDIM   48           // DH / HEADS
#define M_ALL  (T_FR * BATCH * N_TOK)   // 16448 rows (t, bn)
#define M_PAT  (BATCH * T_FR * HW * HW) // 16384 patch tokens (b,t,h,w)
#define KCUBE  27

// ---------------- scratch (device globals; no allocations allowed) ----------------
__device__ float g_t1 [M_ALL * DH];       // fc1 output
__device__ float g_t2 [M_ALL * 64];       // convA output
__device__ float g_xs [M_ALL * DH];       // gelu(xs) then updated in-place by proj residual
__device__ float g_y  [M_PAT * DH];       // LN(patch tokens), (b,t,h,w) row order
__device__ float g_qkv[M_PAT * 3 * DH];   // qkv per patch token: [3][4][48]
__device__ float g_att[M_PAT * DH];       // attention output (pre-proj)

// ---------------- helpers ----------------
__device__ __forceinline__ float gelu_exact(float v) {
    return 0.5f * v * (1.0f + erff(v * 0.70710678118654752f));
}

// map patch row (b,t,h,w) -> xs row (t, bn)
__device__ __forceinline__ int patch_to_xs_row(int pr) {
    int b = pr >> 11;            // /2048
    int t = (pr >> 8) & 7;
    int h = (pr >> 4) & 15;
    int w = pr & 15;
    return t * (BATCH * N_TOK) + b * N_TOK + 1 + (h << 4) + w;
}

// ---------------- generic register-tiled SGEMM: C = A(MxK) @ W(NxK)^T + bias ----------------
// BM=BN=64, BK=32, 256 threads, 4x4 micro-tile.
// mode 0: C[m*N+n] = v
// mode 1: C[m*N+n] = gelu(res[m*N+n] + v)          (convB + residual + gelu)
// mode 2: r = patch_to_xs_row(m); C[r*N+n] += v    (proj + residual scatter into xs)
// mode 3: C[m*N+n] = res[m*N+n] + v                (fc2 + outer residual)
#define BM 64
#define BN 64
#define BK 32

__global__ void gemm_kernel(const float* __restrict__ A,
                            const float* __restrict__ W,
                            const float* __restrict__ bias,
                            float* __restrict__ C,
                            int M, int N, int Kc, int mode,
                            const float* __restrict__ res)
{
    __shared__ float sA[BK][BM + 1];
    __shared__ float sB[BK][BN + 1];

    const int tid = threadIdx.x;          // 0..255
    const int tx  = tid & 15;             // n-dir
    const int ty  = tid >> 4;             // m-dir
    const int m0  = blockIdx.y * BM;
    const int n0  = blockIdx.x * BN;

    const int lc = tid & 31;              // k within tile
    const int lr = tid >> 5;              // 0..7

    float acc[4][4] = {};

    for (int k0 = 0; k0 < Kc; k0 += BK) {
        #pragma unroll
        for (int rr = 0; rr < 8; rr++) {
            int row = lr + rr * 8;
            sA[lc][row] = A[(size_t)(m0 + row) * Kc + k0 + lc];
            sB[lc][row] = W[(size_t)(n0 + row) * Kc + k0 + lc];
        }
        __syncthreads();

        #pragma unroll
        for (int k = 0; k < BK; k++) {
            float a[4], b[4];
            #pragma unroll
            for (int i = 0; i < 4; i++) a[i] = sA[k][ty * 4 + i];
            #pragma unroll
            for (int j = 0; j < 4; j++) b[j] = sB[k][tx * 4 + j];
            #pragma unroll
            for (int i = 0; i < 4; i++)
                #pragma unroll
                for (int j = 0; j < 4; j++)
                    acc[i][j] = fmaf(a[i], b[j], acc[i][j]);
        }
        __syncthreads();
    }

    #pragma unroll
    for (int i = 0; i < 4; i++) {
        int m = m0 + ty * 4 + i;
        #pragma unroll
        for (int j = 0; j < 4; j++) {
            int n = n0 + tx * 4 + j;
            float v = acc[i][j] + bias[n];
            if (mode == 0) {
                C[(size_t)m * N + n] = v;
            } else if (mode == 1) {
                float s = res[(size_t)m * N + n] + v;
                C[(size_t)m * N + n] = gelu_exact(s);
            } else if (mode == 2) {
                int r = patch_to_xs_row(m);
                C[(size_t)r * N + n] += v;
            } else {
                C[(size_t)m * N + n] = res[(size_t)m * N + n] + v;
            }
        }
    }
}

// ---------------- LayerNorm over C=192 for patch tokens ----------------
__global__ void ln_kernel(const float* __restrict__ xs,
                          const float* __restrict__ gamma,
                          const float* __restrict__ beta,
                          float* __restrict__ y)
{
    const int pr  = blockIdx.x;           // 0..16383
    const int tid = threadIdx.x;          // 0..191
    const int row = patch_to_xs_row(pr);

    float v = xs[(size_t)row * DH + tid];

    __shared__ float red[40];

    // mean
    float s = v;
    #pragma unroll
    for (int off = 16; off > 0; off >>= 1) s += __shfl_down_sync(0xffffffff, s, off);
    if ((tid & 31) == 0) red[tid >> 5] = s;
    __syncthreads();
    if (tid == 0) {
        float tot = 0.f;
        #pragma unroll
        for (int i = 0; i < 6; i++) tot += red[i];
        red[32] = tot * (1.0f / DH);
    }
    __syncthreads();
    float mu = red[32];

    // variance
    float d  = v - mu;
    float s2 = d * d;
    #pragma unroll
    for (int off = 16; off > 0; off >>= 1) s2 += __shfl_down_sync(0xffffffff, s2, off);
    if ((tid & 31) == 0) red[8 + (tid >> 5)] = s2;
    __syncthreads();
    if (tid == 0) {
        float tot = 0.f;
        #pragma unroll
        for (int i = 0; i < 6; i++) tot += red[8 + i];
        red[33] = rsqrtf(tot * (1.0f / DH) + 1e-5f);
    }
    __syncthreads();

    y[(size_t)pr * DH + tid] = d * red[33] * gamma[tid] + beta[tid];
}

// ---------------- 3D neighborhood attention (K=3, 27 neighbors, 4 heads, d=48) ----------------
__global__ void attn_kernel(const float* __restrict__ qkv,
                            const float* __restrict__ rpb,
                            float* __restrict__ att)
{
    const int pr  = blockIdx.x;           // token
    const int tid = threadIdx.x;          // 0..191
    const int b = pr >> 11;
    const int t = (pr >> 8) & 7;
    const int h = (pr >> 4) & 15;
    const int w = pr & 15;

    __shared__ float s_q[DH];
    __shared__ int   s_nbr[KCUBE];
    __shared__ float s_sc[HEADS * KCUBE];
    __shared__ float s_p [HEADS * KCUBE];

    const float scale = 0.144337567297406f;   // 48^-0.5
    s_q[tid] = qkv[(size_t)pr * (3 * DH) + tid] * scale;

    const int st = min(max(t - 1, 0), T_FR - 3);
    const int sh = min(max(h - 1, 0), HW - 3);
    const int sw = min(max(w - 1, 0), HW - 3);

    if (tid < KCUBE) {
        int kt = tid / 9, kh = (tid / 3) % 3, kw = tid % 3;
        s_nbr[tid] = (((b * T_FR + st + kt) * HW) + sh + kh) * HW + sw + kw;
    }
    __syncthreads();

    // scores: one thread per (head, neighbor)
    if (tid < HEADS * KCUBE) {
        int head = tid / KCUBE, nb = tid % KCUBE;
        const float* kp = qkv + (size_t)s_nbr[nb] * (3 * DH) + DH + head * HDIM;
        const float* qp = s_q + head * HDIM;
        float s = 0.f;
        #pragma unroll
        for (int j = 0; j < HDIM; j++) s = fmaf(qp[j], kp[j], s);
        int kt = nb / 9, kh = (nb / 3) % 3, kw = nb % 3;
        int rt = st + kt - t + 2;
        int rh = sh + kh - h + 2;
        int rw = sw + kw - w + 2;
        s += rpb[((head * 5 + rt) * 5 + rh) * 5 + rw];
        s_sc[tid] = s;
    }
    __syncthreads();

    // softmax per head (serial over 27, one thread per head — tiny)
    if (tid < HEADS) {
        float mx = -1e30f;
        #pragma unroll
        for (int i = 0; i < KCUBE; i++) mx = fmaxf(mx, s_sc[tid * KCUBE + i]);
        float sum = 0.f;
        #pragma unroll
        for (int i = 0; i < KCUBE; i++) {
            float e = __expf(s_sc[tid * KCUBE + i] - mx);
            s_p[tid * KCUBE + i] = e;
            sum += e;
        }
        float inv = 1.0f / sum;
        #pragma unroll
        for (int i = 0; i < KCUBE; i++) s_p[tid * KCUBE + i] *= inv;
    }
    __syncthreads();

    // output: one thread per channel c = head*48 + j, coalesced V reads
    {
        int head = tid / HDIM;
        float o = 0.f;
        #pragma unroll
        for (int nb = 0; nb < KCUBE; nb++)
            o = fmaf(s_p[head * KCUBE + nb],
                     qkv[(size_t)s_nbr[nb] * (3 * DH) + 2 * DH + tid], o);
        att[(size_t)pr * DH + tid] = o;
    }
}

// ---------------- launch ----------------
extern "C" void kernel_launch(void* const* d_in, const int* in_sizes, int n_in,
                              void* d_out, int out_size)
{
    const float* x       = (const float*)d_in[0];
    const float* fc1_w   = (const float*)d_in[1];
    const float* fc1_b   = (const float*)d_in[2];
    const float* convA_w = (const float*)d_in[3];
    const float* convA_b = (const float*)d_in[4];
    const float* convB_w = (const float*)d_in[5];
    const float* convB_b = (const float*)d_in[6];
    const float* ln_g    = (const float*)d_in[7];
    const float* ln_b    = (const float*)d_in[8];
    const float* qkv_w   = (const float*)d_in[9];
    const float* qkv_b   = (const float*)d_in[10];
    const float* rpb     = (const float*)d_in[11];
    const float* proj_w  = (const float*)d_in[12];
    const float* proj_b  = (const float*)d_in[13];
    const float* fc2_w   = (const float*)d_in[14];
    const float* fc2_b   = (const float*)d_in[15];
    float* out = (float*)d_out;

    float *t1, *t2, *xs, *y, *qkv, *att;
    cudaGetSymbolAddress((void**)&t1,  g_t1);
    cudaGetSymbolAddress((void**)&t2,  g_t2);
    cudaGetSymbolAddress((void**)&xs,  g_xs);
    cudaGetSymbolAddress((void**)&y,   g_y);
    cudaGetSymbolAddress((void**)&qkv, g_qkv);
    cudaGetSymbolAddress((void**)&att, g_att);

    // 1) fc1: (16448x768) @ (192x768)^T -> t1
    gemm_kernel<<<dim3(DH / BN, M_ALL / BM), 256>>>(x, fc1_w, fc1_b, t1,
                                                    M_ALL, DH, D_MOD, 0, nullptr);
    // 2) convA: (16448x192) @ (64x192)^T -> t2
    gemm_kernel<<<dim3(64 / BN, M_ALL / BM), 256>>>(t1, convA_w, convA_b, t2,
                                                    M_ALL, 64, DH, 0, nullptr);
    // 3) convB + residual + gelu -> xs
    gemm_kernel<<<dim3(DH / BN, M_ALL / BM), 256>>>(t2, convB_w, convB_b, xs,
                                                    M_ALL, DH, 64, 1, t1);
    // 4) LayerNorm on patch tokens -> y
    ln_kernel<<<M_PAT, DH>>>(xs, ln_g, ln_b, y);
    // 5) qkv: (16384x192) @ (576x192)^T -> qkv
    gemm_kernel<<<dim3((3 * DH) / BN, M_PAT / BM), 256>>>(y, qkv_w, qkv_b, qkv,
                                                          M_PAT, 3 * DH, DH, 0, nullptr);
    // 6) neighborhood attention -> att
    attn_kernel<<<M_PAT, DH>>>(qkv, rpb, att);
    // 7) proj + scatter residual into xs
    gemm_kernel<<<dim3(DH / BN, M_PAT / BM), 256>>>(att, proj_w, proj_b, xs,
                                                    M_PAT, DH, DH, 2, nullptr);
    // 8) fc2 + outer residual -> out
    gemm_kernel<<<dim3(D_MOD / BN, M_ALL / BM), 256>>>(xs, fc2_w, fc2_b, out,
                                                       M_ALL, D_MOD, DH, 3, x);
}

// round 3
// speedup vs baseline: 1.4952x; 1.4952x over previous
#include <cuda_runtime.h>
#include <math.h>
#include <stdint.h>

// ---------------- problem constants ----------------
#define T_FR   8
#define N_TOK  257
#define HW     16
#define BATCH  8
#define D_MOD  768
#define DH     192
#define HEADS  4
#define HDIM   48
#define M_ALL  (T_FR * BATCH * N_TOK)   // 16448
#define M_PAT  (BATCH * T_FR * HW * HW) // 16384
#define KCUBE  27

// ---------------- scratch ----------------
__device__ float g_t1 [M_ALL * DH];
__device__ float g_t2 [M_ALL * 64];
__device__ float g_xs [M_ALL * DH];
__device__ float g_y  [M_PAT * DH];
__device__ float g_qkv[M_PAT * 3 * DH];
__device__ float g_att[M_PAT * DH];

// ---------------- helpers ----------------
__device__ __forceinline__ float gelu_exact(float v) {
    return 0.5f * v * (1.0f + erff(v * 0.70710678118654752f));
}

__device__ __forceinline__ int patch_to_xs_row(int pr) {
    int b = pr >> 11;
    int t = (pr >> 8) & 7;
    int h = (pr >> 4) & 15;
    int w = pr & 15;
    return t * (BATCH * N_TOK) + b * N_TOK + 1 + (h << 4) + w;
}

// tf32 cvt: destination must be a b32 register ("=r"), not f32.
__device__ __forceinline__ uint32_t to_tf32(float x) {
    uint32_t r;
    asm("cvt.rna.tf32.f32 %0, %1;" : "=r"(r) : "f"(x));
    return r;
}

// ---------------- tf32 tensor-core GEMM ----------------
// C = A(MxK) @ W(NxK)^T + bias, tiles BM=BN=64, BK=32.
// 128 threads = 4 warps in 2x2; each warp owns a 32x32 subtile
// (2 m-frags x 4 n-frags of m16n8k8).
// mode 0: C = v
// mode 1: C = gelu(res + v)
// mode 2: C[patch_to_xs_row(m)] += v
// mode 3: C = res + v
#define BM 64
#define BN 64
#define BK 32
#define SSTR 36   // padded smem stride -> conflict-free fragment loads

__global__ __launch_bounds__(128)
void mma_gemm(const float* __restrict__ A,
              const float* __restrict__ W,
              const float* __restrict__ bias,
              float* __restrict__ C,
              int M, int N, int Kc, int mode,
              const float* __restrict__ res)
{
    __shared__ uint32_t sA[BM * SSTR];
    __shared__ uint32_t sB[BN * SSTR];

    const int tid    = threadIdx.x;
    const int warpid = tid >> 5;
    const int lane   = tid & 31;
    const int m0     = blockIdx.y * BM;
    const int n0     = blockIdx.x * BN;

    const int wm = (warpid >> 1) * 32;   // warp m-offset in tile
    const int wn = (warpid & 1) * 32;    // warp n-offset in tile

    // global-load mapping: each thread loads 16 floats (4 float4) per tile
    const int ldr = tid >> 1;            // row 0..63
    const int ldc = (tid & 1) * 16;      // col base 0 or 16

    const int r = lane >> 2;             // fragment row within 8
    const int c = lane & 3;              // fragment col within 4

    float acc[2][4][4];
    #pragma unroll
    for (int i = 0; i < 2; i++)
        #pragma unroll
        for (int j = 0; j < 4; j++)
            #pragma unroll
            for (int q = 0; q < 4; q++) acc[i][j][q] = 0.f;

    const float* Arow = A + (size_t)(m0 + ldr) * Kc + ldc;
    const float* Wrow = W + (size_t)(n0 + ldr) * Kc + ldc;

    float4 pa[4], pb[4];
    #pragma unroll
    for (int i = 0; i < 4; i++) {
        pa[i] = *(const float4*)(Arow + 4 * i);
        pb[i] = *(const float4*)(Wrow + 4 * i);
    }

    for (int k0 = 0; k0 < Kc; k0 += BK) {
        // stage current tile into smem (tf32-rounded)
        #pragma unroll
        for (int i = 0; i < 4; i++) {
            uint32_t* da = sA + ldr * SSTR + ldc + 4 * i;
            da[0] = to_tf32(pa[i].x); da[1] = to_tf32(pa[i].y);
            da[2] = to_tf32(pa[i].z); da[3] = to_tf32(pa[i].w);
            uint32_t* db = sB + ldr * SSTR + ldc + 4 * i;
            db[0] = to_tf32(pb[i].x); db[1] = to_tf32(pb[i].y);
            db[2] = to_tf32(pb[i].z); db[3] = to_tf32(pb[i].w);
        }
        __syncthreads();

        // prefetch next tile while computing
        if (k0 + BK < Kc) {
            const float* An = Arow + k0 + BK;
            const float* Wn = Wrow + k0 + BK;
            #pragma unroll
            for (int i = 0; i < 4; i++) {
                pa[i] = *(const float4*)(An + 4 * i);
                pb[i] = *(const float4*)(Wn + 4 * i);
            }
        }

        #pragma unroll
        for (int ks = 0; ks < 4; ks++) {
            const int kk = ks * 8;
            uint32_t af[2][4], bf[4][2];
            #pragma unroll
            for (int mi = 0; mi < 2; mi++) {
                const uint32_t* base = sA + (wm + mi * 16 + r) * SSTR + kk + c;
                af[mi][0] = base[0];
                af[mi][1] = base[8 * SSTR];
                af[mi][2] = base[4];
                af[mi][3] = base[8 * SSTR + 4];
            }
            #pragma unroll
            for (int nj = 0; nj < 4; nj++) {
                const uint32_t* base = sB + (wn + nj * 8 + r) * SSTR + kk + c;
                bf[nj][0] = base[0];
                bf[nj][1] = base[4];
            }
            #pragma unroll
            for (int mi = 0; mi < 2; mi++)
                #pragma unroll
                for (int nj = 0; nj < 4; nj++) {
                    float* cc = acc[mi][nj];
                    asm volatile(
                        "mma.sync.aligned.m16n8k8.row.col.f32.tf32.tf32.f32 "
                        "{%0,%1,%2,%3}, {%4,%5,%6,%7}, {%8,%9}, {%0,%1,%2,%3};"
                        : "+f"(cc[0]), "+f"(cc[1]), "+f"(cc[2]), "+f"(cc[3])
                        : "r"(af[mi][0]), "r"(af[mi][1]), "r"(af[mi][2]), "r"(af[mi][3]),
                          "r"(bf[nj][0]), "r"(bf[nj][1]));
                }
        }
        __syncthreads();
    }

    // epilogue
    #pragma unroll
    for (int mi = 0; mi < 2; mi++) {
        #pragma unroll
        for (int nj = 0; nj < 4; nj++) {
            #pragma unroll
            for (int half = 0; half < 2; half++) {      // (row, row+8)
                int m = m0 + wm + mi * 16 + r + half * 8;
                #pragma unroll
                for (int q = 0; q < 2; q++) {
                    int n = n0 + wn + nj * 8 + 2 * c + q;
                    float v = acc[mi][nj][half * 2 + q] + bias[n];
                    if (mode == 0) {
                        C[(size_t)m * N + n] = v;
                    } else if (mode == 1) {
                        float s = res[(size_t)m * N + n] + v;
                        C[(size_t)m * N + n] = gelu_exact(s);
                    } else if (mode == 2) {
                        int rr = patch_to_xs_row(m);
                        C[(size_t)rr * N + n] += v;
                    } else {
                        C[(size_t)m * N + n] = res[(size_t)m * N + n] + v;
                    }
                }
            }
        }
    }
}

// ---------------- LayerNorm over C=192 for patch tokens ----------------
__global__ void ln_kernel(const float* __restrict__ xs,
                          const float* __restrict__ gamma,
                          const float* __restrict__ beta,
                          float* __restrict__ y)
{
    const int pr  = blockIdx.x;
    const int tid = threadIdx.x;
    const int row = patch_to_xs_row(pr);

    float v = xs[(size_t)row * DH + tid];

    __shared__ float red[40];

    float s = v;
    #pragma unroll
    for (int off = 16; off > 0; off >>= 1) s += __shfl_down_sync(0xffffffff, s, off);
    if ((tid & 31) == 0) red[tid >> 5] = s;
    __syncthreads();
    if (tid == 0) {
        float tot = 0.f;
        #pragma unroll
        for (int i = 0; i < 6; i++) tot += red[i];
        red[32] = tot * (1.0f / DH);
    }
    __syncthreads();
    float mu = red[32];

    float d  = v - mu;
    float s2 = d * d;
    #pragma unroll
    for (int off = 16; off > 0; off >>= 1) s2 += __shfl_down_sync(0xffffffff, s2, off);
    if ((tid & 31) == 0) red[8 + (tid >> 5)] = s2;
    __syncthreads();
    if (tid == 0) {
        float tot = 0.f;
        #pragma unroll
        for (int i = 0; i < 6; i++) tot += red[8 + i];
        red[33] = rsqrtf(tot * (1.0f / DH) + 1e-5f);
    }
    __syncthreads();

    y[(size_t)pr * DH + tid] = d * red[33] * gamma[tid] + beta[tid];
}

// ---------------- 3D neighborhood attention ----------------
__global__ void attn_kernel(const float* __restrict__ qkv,
                            const float* __restrict__ rpb,
                            float* __restrict__ att)
{
    const int pr  = blockIdx.x;
    const int tid = threadIdx.x;
    const int b = pr >> 11;
    const int t = (pr >> 8) & 7;
    const int h = (pr >> 4) & 15;
    const int w = pr & 15;

    __shared__ float s_q[DH];
    __shared__ int   s_nbr[KCUBE];
    __shared__ float s_sc[HEADS * KCUBE];
    __shared__ float s_p [HEADS * KCUBE];

    const float scale = 0.144337567297406f;   // 48^-0.5
    s_q[tid] = qkv[(size_t)pr * (3 * DH) + tid] * scale;

    const int st = min(max(t - 1, 0), T_FR - 3);
    const int sh = min(max(h - 1, 0), HW - 3);
    const int sw = min(max(w - 1, 0), HW - 3);

    if (tid < KCUBE) {
        int kt = tid / 9, kh = (tid / 3) % 3, kw = tid % 3;
        s_nbr[tid] = (((b * T_FR + st + kt) * HW) + sh + kh) * HW + sw + kw;
    }
    __syncthreads();

    if (tid < HEADS * KCUBE) {
        int head = tid / KCUBE, nb = tid % KCUBE;
        const float* kp = qkv + (size_t)s_nbr[nb] * (3 * DH) + DH + head * HDIM;
        const float* qp = s_q + head * HDIM;
        float s = 0.f;
        #pragma unroll
        for (int j = 0; j < HDIM; j++) s = fmaf(qp[j], kp[j], s);
        int kt = nb / 9, kh = (nb / 3) % 3, kw = nb % 3;
        int rt = st + kt - t + 2;
        int rh = sh + kh - h + 2;
        int rw = sw + kw - w + 2;
        s += rpb[((head * 5 + rt) * 5 + rh) * 5 + rw];
        s_sc[tid] = s;
    }
    __syncthreads();

    if (tid < HEADS) {
        float mx = -1e30f;
        #pragma unroll
        for (int i = 0; i < KCUBE; i++) mx = fmaxf(mx, s_sc[tid * KCUBE + i]);
        float sum = 0.f;
        #pragma unroll
        for (int i = 0; i < KCUBE; i++) {
            float e = __expf(s_sc[tid * KCUBE + i] - mx);
            s_p[tid * KCUBE + i] = e;
            sum += e;
        }
        float inv = 1.0f / sum;
        #pragma unroll
        for (int i = 0; i < KCUBE; i++) s_p[tid * KCUBE + i] *= inv;
    }
    __syncthreads();

    {
        int head = tid / HDIM;
        float o = 0.f;
        #pragma unroll
        for (int nb = 0; nb < KCUBE; nb++)
            o = fmaf(s_p[head * KCUBE + nb],
                     qkv[(size_t)s_nbr[nb] * (3 * DH) + 2 * DH + tid], o);
        att[(size_t)pr * DH + tid] = o;
    }
}

// ---------------- launch ----------------
extern "C" void kernel_launch(void* const* d_in, const int* in_sizes, int n_in,
                              void* d_out, int out_size)
{
    const float* x       = (const float*)d_in[0];
    const float* fc1_w   = (const float*)d_in[1];
    const float* fc1_b   = (const float*)d_in[2];
    const float* convA_w = (const float*)d_in[3];
    const float* convA_b = (const float*)d_in[4];
    const float* convB_w = (const float*)d_in[5];
    const float* convB_b = (const float*)d_in[6];
    const float* ln_g    = (const float*)d_in[7];
    const float* ln_b    = (const float*)d_in[8];
    const float* qkv_w   = (const float*)d_in[9];
    const float* qkv_b   = (const float*)d_in[10];
    const float* rpb     = (const float*)d_in[11];
    const float* proj_w  = (const float*)d_in[12];
    const float* proj_b  = (const float*)d_in[13];
    const float* fc2_w   = (const float*)d_in[14];
    const float* fc2_b   = (const float*)d_in[15];
    float* out = (float*)d_out;

    float *t1, *t2, *xs, *y, *qkv, *att;
    cudaGetSymbolAddress((void**)&t1,  g_t1);
    cudaGetSymbolAddress((void**)&t2,  g_t2);
    cudaGetSymbolAddress((void**)&xs,  g_xs);
    cudaGetSymbolAddress((void**)&y,   g_y);
    cudaGetSymbolAddress((void**)&qkv, g_qkv);
    cudaGetSymbolAddress((void**)&att, g_att);

    // 1) fc1
    mma_gemm<<<dim3(DH / BN, M_ALL / BM), 128>>>(x, fc1_w, fc1_b, t1,
                                                 M_ALL, DH, D_MOD, 0, nullptr);
    // 2) convA
    mma_gemm<<<dim3(64 / BN, M_ALL / BM), 128>>>(t1, convA_w, convA_b, t2,
                                                 M_ALL, 64, DH, 0, nullptr);
    // 3) convB + residual + gelu
    mma_gemm<<<dim3(DH / BN, M_ALL / BM), 128>>>(t2, convB_w, convB_b, xs,
                                                 M_ALL, DH, 64, 1, t1);
    // 4) LayerNorm
    ln_kernel<<<M_PAT, DH>>>(xs, ln_g, ln_b, y);
    // 5) qkv
    mma_gemm<<<dim3((3 * DH) / BN, M_PAT / BM), 128>>>(y, qkv_w, qkv_b, qkv,
                                                       M_PAT, 3 * DH, DH, 0, nullptr);
    // 6) attention
    attn_kernel<<<M_PAT, DH>>>(qkv, rpb, att);
    // 7) proj + scatter residual
    mma_gemm<<<dim3(DH / BN, M_PAT / BM), 128>>>(att, proj_w, proj_b, xs,
                                                 M_PAT, DH, DH, 2, nullptr);
    // 8) fc2 + outer residual
    mma_gemm<<<dim3(D_MOD / BN, M_ALL / BM), 128>>>(xs, fc2_w, fc2_b, out,
                                                    M_ALL, D_MOD, DH, 3, x);
}

// round 4
// speedup vs baseline: 2.2181x; 1.4834x over previous
#include <cuda_runtime.h>
#include <math.h>
#include <stdint.h>

// ---------------- problem constants ----------------
#define T_FR   8
#define N_TOK  257
#define HW     16
#define BATCH  8
#define D_MOD  768
#define DH     192
#define HEADS  4
#define HDIM   48
#define M_ALL  (T_FR * BATCH * N_TOK)   // 16448
#define M_PAT  (BATCH * T_FR * HW * HW) // 16384
#define KCUBE  27

// ---------------- scratch ----------------
__device__ float g_t1 [M_ALL * DH];
__device__ float g_t2 [M_ALL * 64];
__device__ float g_xs [M_ALL * DH];
__device__ float g_y  [M_PAT * DH];
__device__ float g_qkv[M_PAT * 3 * DH];
__device__ float g_att[M_PAT * DH];

// ---------------- helpers ----------------
__device__ __forceinline__ float gelu_exact(float v) {
    return 0.5f * v * (1.0f + erff(v * 0.70710678118654752f));
}

__device__ __forceinline__ int patch_to_xs_row(int pr) {
    int b = pr >> 11;
    int t = (pr >> 8) & 7;
    int h = (pr >> 4) & 15;
    int w = pr & 15;
    return t * (BATCH * N_TOK) + b * N_TOK + 1 + (h << 4) + w;
}

// pack two fp32 into bf16x2 (lo = first arg)
__device__ __forceinline__ uint32_t pack_bf2(float lo, float hi) {
    uint32_t r;
    asm("cvt.rn.bf16x2.f32 %0, %1, %2;" : "=r"(r) : "f"(hi), "f"(lo));
    return r;
}

// ---------------- bf16 tensor-core GEMM ----------------
// C = A(MxK) @ W(NxK)^T + bias. BM=128, BN=64, BK=32, 256 threads (8 warps 4x2).
// Each warp: 32x32 subtile = 2 m-frags x 4 n-frags of m16n8k16.
// smem holds packed bf16x2 pairs: row stride SSTR=20 u32 (conflict-free frags).
// mode 0: C = v ; mode 1: C = gelu(res+v) ; mode 2: C[map(m)] += v ; mode 3: C = res+v
#define BM 128
#define BN 64
#define BK 32
#define KP 16       // BK/2 u32 per row
#define SSTR 20     // padded u32 stride

__global__ __launch_bounds__(256)
void mma_gemm(const float* __restrict__ A,
              const float* __restrict__ W,
              const float* __restrict__ bias,
              float* __restrict__ C,
              int M, int N, int Kc, int mode,
              const float* __restrict__ res)
{
    __shared__ uint32_t sA[BM * SSTR];
    __shared__ uint32_t sB[BN * SSTR];

    const int tid    = threadIdx.x;
    const int warpid = tid >> 5;
    const int lane   = tid & 31;
    const int m0     = blockIdx.y * BM;
    const int n0     = blockIdx.x * BN;

    const int wm = (warpid >> 1) * 32;   // 0,32,64,96
    const int wn = (warpid & 1) * 32;    // 0,32

    // A tile: 128 rows x 32 cols, 2 threads/row, 16 floats each
    const int ldrA = tid >> 1;
    const int ldcA = (tid & 1) * 16;
    // B tile: 64 rows x 32 cols, 4 threads/row, 8 floats each
    const int ldrB = tid >> 2;
    const int ldcB = (tid & 3) * 8;

    const int r = lane >> 2;             // 0..7
    const int c = lane & 3;              // 0..3

    float acc[2][4][4];
    #pragma unroll
    for (int i = 0; i < 2; i++)
        #pragma unroll
        for (int j = 0; j < 4; j++)
            #pragma unroll
            for (int q = 0; q < 4; q++) acc[i][j][q] = 0.f;

    const int growA = min(m0 + ldrA, M - 1);      // clamp (last block may overhang)
    const float* Arow = A + (size_t)growA * Kc + ldcA;
    const float* Wrow = W + (size_t)(n0 + ldrB) * Kc + ldcB;

    float4 pa[4], pb[2];
    #pragma unroll
    for (int i = 0; i < 4; i++) pa[i] = *(const float4*)(Arow + 4 * i);
    #pragma unroll
    for (int i = 0; i < 2; i++) pb[i] = *(const float4*)(Wrow + 4 * i);

    for (int k0 = 0; k0 < Kc; k0 += BK) {
        // stage current tile into smem as packed bf16x2
        {
            uint32_t* da = sA + ldrA * SSTR + (ldcA >> 1);
            #pragma unroll
            for (int i = 0; i < 4; i++) {
                da[2 * i]     = pack_bf2(pa[i].x, pa[i].y);
                da[2 * i + 1] = pack_bf2(pa[i].z, pa[i].w);
            }
            uint32_t* db = sB + ldrB * SSTR + (ldcB >> 1);
            #pragma unroll
            for (int i = 0; i < 2; i++) {
                db[2 * i]     = pack_bf2(pb[i].x, pb[i].y);
                db[2 * i + 1] = pack_bf2(pb[i].z, pb[i].w);
            }
        }
        __syncthreads();

        // prefetch next tile
        if (k0 + BK < Kc) {
            const float* An = Arow + k0 + BK;
            const float* Wn = Wrow + k0 + BK;
            #pragma unroll
            for (int i = 0; i < 4; i++) pa[i] = *(const float4*)(An + 4 * i);
            #pragma unroll
            for (int i = 0; i < 2; i++) pb[i] = *(const float4*)(Wn + 4 * i);
        }

        #pragma unroll
        for (int ks = 0; ks < 2; ks++) {
            const int kk = ks * 8;
            uint32_t af[2][4], bf[4][2];
            #pragma unroll
            for (int mi = 0; mi < 2; mi++) {
                const uint32_t* base = sA + (wm + mi * 16 + r) * SSTR + kk + c;
                af[mi][0] = base[0];
                af[mi][1] = base[8 * SSTR];
                af[mi][2] = base[4];
                af[mi][3] = base[8 * SSTR + 4];
            }
            #pragma unroll
            for (int nj = 0; nj < 4; nj++) {
                const uint32_t* base = sB + (wn + nj * 8 + r) * SSTR + kk + c;
                bf[nj][0] = base[0];
                bf[nj][1] = base[4];
            }
            #pragma unroll
            for (int mi = 0; mi < 2; mi++)
                #pragma unroll
                for (int nj = 0; nj < 4; nj++) {
                    float* cc = acc[mi][nj];
                    asm volatile(
                        "mma.sync.aligned.m16n8k16.row.col.f32.bf16.bf16.f32 "
                        "{%0,%1,%2,%3}, {%4,%5,%6,%7}, {%8,%9}, {%0,%1,%2,%3};"
                        : "+f"(cc[0]), "+f"(cc[1]), "+f"(cc[2]), "+f"(cc[3])
                        : "r"(af[mi][0]), "r"(af[mi][1]), "r"(af[mi][2]), "r"(af[mi][3]),
                          "r"(bf[nj][0]), "r"(bf[nj][1]));
                }
        }
        __syncthreads();
    }

    // epilogue
    #pragma unroll
    for (int mi = 0; mi < 2; mi++) {
        #pragma unroll
        for (int half = 0; half < 2; half++) {
            int m = m0 + wm + mi * 16 + r + half * 8;
            if (m >= M) continue;
            #pragma unroll
            for (int nj = 0; nj < 4; nj++) {
                #pragma unroll
                for (int q = 0; q < 2; q++) {
                    int n = n0 + wn + nj * 8 + 2 * c + q;
                    float v = acc[mi][nj][half * 2 + q] + bias[n];
                    if (mode == 0) {
                        C[(size_t)m * N + n] = v;
                    } else if (mode == 1) {
                        float s = res[(size_t)m * N + n] + v;
                        C[(size_t)m * N + n] = gelu_exact(s);
                    } else if (mode == 2) {
                        int rr = patch_to_xs_row(m);
                        C[(size_t)rr * N + n] += v;
                    } else {
                        C[(size_t)m * N + n] = res[(size_t)m * N + n] + v;
                    }
                }
            }
        }
    }
}

// ---------------- LayerNorm over C=192 for patch tokens ----------------
__global__ void ln_kernel(const float* __restrict__ xs,
                          const float* __restrict__ gamma,
                          const float* __restrict__ beta,
                          float* __restrict__ y)
{
    const int pr  = blockIdx.x;
    const int tid = threadIdx.x;
    const int row = patch_to_xs_row(pr);

    float v = xs[(size_t)row * DH + tid];

    __shared__ float red[40];

    float s = v;
    #pragma unroll
    for (int off = 16; off > 0; off >>= 1) s += __shfl_down_sync(0xffffffff, s, off);
    if ((tid & 31) == 0) red[tid >> 5] = s;
    __syncthreads();
    if (tid == 0) {
        float tot = 0.f;
        #pragma unroll
        for (int i = 0; i < 6; i++) tot += red[i];
        red[32] = tot * (1.0f / DH);
    }
    __syncthreads();
    float mu = red[32];

    float d  = v - mu;
    float s2 = d * d;
    #pragma unroll
    for (int off = 16; off > 0; off >>= 1) s2 += __shfl_down_sync(0xffffffff, s2, off);
    if ((tid & 31) == 0) red[8 + (tid >> 5)] = s2;
    __syncthreads();
    if (tid == 0) {
        float tot = 0.f;
        #pragma unroll
        for (int i = 0; i < 6; i++) tot += red[8 + i];
        red[33] = rsqrtf(tot * (1.0f / DH) + 1e-5f);
    }
    __syncthreads();

    y[(size_t)pr * DH + tid] = d * red[33] * gamma[tid] + beta[tid];
}

// ---------------- 3D neighborhood attention (smem-staged K) ----------------
#define KROW 193    // padded smem row stride for K tiles

__global__ void attn_kernel(const float* __restrict__ qkv,
                            const float* __restrict__ rpb,
                            float* __restrict__ att)
{
    const int pr  = blockIdx.x;
    const int tid = threadIdx.x;
    const int b = pr >> 11;
    const int t = (pr >> 8) & 7;
    const int h = (pr >> 4) & 15;
    const int w = pr & 15;

    __shared__ float s_k[KCUBE * KROW];
    __shared__ float s_q[DH];
    __shared__ int   s_nbr[KCUBE];
    __shared__ float s_sc[HEADS * KCUBE];
    __shared__ float s_p [HEADS * KCUBE];

    const float scale = 0.144337567297406f;   // 48^-0.5
    s_q[tid] = qkv[(size_t)pr * (3 * DH) + tid] * scale;

    const int st = min(max(t - 1, 0), T_FR - 3);
    const int sh = min(max(h - 1, 0), HW - 3);
    const int sw = min(max(w - 1, 0), HW - 3);

    if (tid < KCUBE) {
        int kt = tid / 9, kh = (tid / 3) % 3, kw = tid % 3;
        s_nbr[tid] = (((b * T_FR + st + kt) * HW) + sh + kh) * HW + sw + kw;
    }
    __syncthreads();

    // stage 27 K rows, fully coalesced (192 threads = one row per iter)
    #pragma unroll 4
    for (int nb = 0; nb < KCUBE; nb++)
        s_k[nb * KROW + tid] = qkv[(size_t)s_nbr[nb] * (3 * DH) + DH + tid];
    __syncthreads();

    // scores from smem: one thread per (head, neighbor)
    if (tid < HEADS * KCUBE) {
        int head = tid / KCUBE, nb = tid % KCUBE;
        const float* kp = s_k + nb * KROW + head * HDIM;
        const float* qp = s_q + head * HDIM;
        float s = 0.f;
        #pragma unroll
        for (int j = 0; j < HDIM; j++) s = fmaf(qp[j], kp[j], s);
        int kt = nb / 9, kh = (nb / 3) % 3, kw = nb % 3;
        int rt = st + kt - t + 2;
        int rh = sh + kh - h + 2;
        int rw = sw + kw - w + 2;
        s += rpb[((head * 5 + rt) * 5 + rh) * 5 + rw];
        s_sc[tid] = s;
    }
    __syncthreads();

    if (tid < HEADS) {
        float mx = -1e30f;
        #pragma unroll
        for (int i = 0; i < KCUBE; i++) mx = fmaxf(mx, s_sc[tid * KCUBE + i]);
        float sum = 0.f;
        #pragma unroll
        for (int i = 0; i < KCUBE; i++) {
            float e = __expf(s_sc[tid * KCUBE + i] - mx);
            s_p[tid * KCUBE + i] = e;
            sum += e;
        }
        float inv = 1.0f / sum;
        #pragma unroll
        for (int i = 0; i < KCUBE; i++) s_p[tid * KCUBE + i] *= inv;
    }
    __syncthreads();

    // output: one thread per channel, coalesced V reads (L2-resident)
    {
        int head = tid / HDIM;
        float o = 0.f;
        #pragma unroll
        for (int nb = 0; nb < KCUBE; nb++)
            o = fmaf(s_p[head * KCUBE + nb],
                     qkv[(size_t)s_nbr[nb] * (3 * DH) + 2 * DH + tid], o);
        att[(size_t)pr * DH + tid] = o;
    }
}

// ---------------- launch ----------------
extern "C" void kernel_launch(void* const* d_in, const int* in_sizes, int n_in,
                              void* d_out, int out_size)
{
    const float* x       = (const float*)d_in[0];
    const float* fc1_w   = (const float*)d_in[1];
    const float* fc1_b   = (const float*)d_in[2];
    const float* convA_w = (const float*)d_in[3];
    const float* convA_b = (const float*)d_in[4];
    const float* convB_w = (const float*)d_in[5];
    const float* convB_b = (const float*)d_in[6];
    const float* ln_g    = (const float*)d_in[7];
    const float* ln_b    = (const float*)d_in[8];
    const float* qkv_w   = (const float*)d_in[9];
    const float* qkv_b   = (const float*)d_in[10];
    const float* rpb     = (const float*)d_in[11];
    const float* proj_w  = (const float*)d_in[12];
    const float* proj_b  = (const float*)d_in[13];
    const float* fc2_w   = (const float*)d_in[14];
    const float* fc2_b   = (const float*)d_in[15];
    float* out = (float*)d_out;

    float *t1, *t2, *xs, *y, *qkv, *att;
    cudaGetSymbolAddress((void**)&t1,  g_t1);
    cudaGetSymbolAddress((void**)&t2,  g_t2);
    cudaGetSymbolAddress((void**)&xs,  g_xs);
    cudaGetSymbolAddress((void**)&y,   g_y);
    cudaGetSymbolAddress((void**)&qkv, g_qkv);
    cudaGetSymbolAddress((void**)&att, g_att);

    const int gyA = (M_ALL + BM - 1) / BM;   // 129
    const int gyP = M_PAT / BM;              // 128

    // 1) fc1
    mma_gemm<<<dim3(DH / BN, gyA), 256>>>(x, fc1_w, fc1_b, t1,
                                          M_ALL, DH, D_MOD, 0, nullptr);
    // 2) convA
    mma_gemm<<<dim3(64 / BN, gyA), 256>>>(t1, convA_w, convA_b, t2,
                                          M_ALL, 64, DH, 0, nullptr);
    // 3) convB + residual + gelu
    mma_gemm<<<dim3(DH / BN, gyA), 256>>>(t2, convB_w, convB_b, xs,
                                          M_ALL, DH, 64, 1, t1);
    // 4) LayerNorm
    ln_kernel<<<M_PAT, DH>>>(xs, ln_g, ln_b, y);
    // 5) qkv
    mma_gemm<<<dim3((3 * DH) / BN, gyP), 256>>>(y, qkv_w, qkv_b, qkv,
                                                M_PAT, 3 * DH, DH, 0, nullptr);
    // 6) attention
    attn_kernel<<<M_PAT, DH>>>(qkv, rpb, att);
    // 7) proj + scatter residual
    mma_gemm<<<dim3(DH / BN, gyP), 256>>>(att, proj_w, proj_b, xs,
                                          M_PAT, DH, DH, 2, nullptr);
    // 8) fc2 + outer residual
    mma_gemm<<<dim3(D_MOD / BN, gyA), 256>>>(xs, fc2_w, fc2_b, out,
                                             M_ALL, D_MOD, DH, 3, x);
}

// round 6
// speedup vs baseline: 2.8290x; 1.2754x over previous
#include <cuda_runtime.h>
#include <cuda_bf16.h>
#include <math.h>
#include <stdint.h>

// ---------------- problem constants ----------------
#define T_FR   8
#define N_TOK  257
#define HW     16
#define BATCH  8
#define D_MOD  768
#define DH     192
#define HEADS  4
#define HDIM   48
#define M_ALL  (T_FR * BATCH * N_TOK)   // 16448
#define M_PAT  (BATCH * T_FR * HW * HW) // 16384
#define KCUBE  27

// ---------------- scratch ----------------
__device__ float g_t1 [M_ALL * DH];       // fc1 out fp32 (residual for convB)
__device__ float g_xs [M_ALL * DH];       // gelu out fp32 (LN input, mode2 source)
__device__ float g_qkv[M_PAT * 3 * DH];   // qkv fp32 (attention input)

__device__ __nv_bfloat16 g_xb  [M_ALL * D_MOD];   // x in bf16
__device__ __nv_bfloat16 g_t1b [M_ALL * DH];
__device__ __nv_bfloat16 g_t2b [M_ALL * 64];
__device__ __nv_bfloat16 g_xsb [M_ALL * DH];
__device__ __nv_bfloat16 g_yb  [M_PAT * DH];
__device__ __nv_bfloat16 g_attb[M_PAT * DH];

__device__ __nv_bfloat16 g_w_fc1 [DH * D_MOD];
__device__ __nv_bfloat16 g_w_cA  [64 * DH];
__device__ __nv_bfloat16 g_w_cB  [DH * 64];
__device__ __nv_bfloat16 g_w_qkv [3 * DH * DH];
__device__ __nv_bfloat16 g_w_proj[DH * DH];
__device__ __nv_bfloat16 g_w_fc2 [D_MOD * DH];

// ---------------- helpers ----------------
__device__ __forceinline__ float gelu_exact(float v) {
    return 0.5f * v * (1.0f + erff(v * 0.70710678118654752f));
}

__device__ __forceinline__ int patch_to_xs_row(int pr) {
    int b = pr >> 11;
    int t = (pr >> 8) & 7;
    int h = (pr >> 4) & 15;
    int w = pr & 15;
    return t * (BATCH * N_TOK) + b * N_TOK + 1 + (h << 4) + w;
}

__device__ __forceinline__ uint32_t pack_bf2(float lo, float hi) {
    uint32_t r;
    asm("cvt.rn.bf16x2.f32 %0, %1, %2;" : "=r"(r) : "f"(hi), "f"(lo));
    return r;
}

__device__ __forceinline__ uint32_t smem_u32(const void* p) {
    uint32_t a;
    asm("{ .reg .u64 t; cvta.to.shared.u64 t, %1; cvt.u32.u64 %0, t; }"
        : "=r"(a) : "l"(p));
    return a;
}

#define CP16(dst, src) \
    asm volatile("cp.async.cg.shared.global [%0], [%1], 16;" \
        :: "r"(dst), "l"(src) : "memory")
#define CP_COMMIT() asm volatile("cp.async.commit_group;" ::: "memory")
#define CP_WAIT(N)  asm volatile("cp.async.wait_group %0;" :: "n"(N) : "memory")

#define LDSM4(r0, r1, r2, r3, addr) \
    asm volatile("ldmatrix.sync.aligned.m8n8.x4.shared.b16 {%0,%1,%2,%3}, [%4];" \
        : "=r"(r0), "=r"(r1), "=r"(r2), "=r"(r3) : "r"(addr))

#define MMA16816(cc, A0, A1, A2, A3, B0, B1) \
    asm volatile("mma.sync.aligned.m16n8k16.row.col.f32.bf16.bf16.f32 " \
        "{%0,%1,%2,%3}, {%4,%5,%6,%7}, {%8,%9}, {%0,%1,%2,%3};" \
        : "+f"((cc)[0]), "+f"((cc)[1]), "+f"((cc)[2]), "+f"((cc)[3]) \
        : "r"(A0), "r"(A1), "r"(A2), "r"(A3), "r"(B0), "r"(B1))

// ---------------- bf16 GEMM: cp.async + ldmatrix + mma.sync ----------------
// C = A(MxK,bf16) @ W(NxK,bf16)^T + bias. BM=128, BN=64, BK=32. 256 thr, 8 warps 4x2.
// smem rows padded to 40 bf16 (80B) -> conflict-free ldmatrix & cp.async.
// MODE 0: v ; 1: gelu(res[m]+v) ; 2: res[rr]+v stored at rr ; 3: res[m]+v
#define ASTRIDE 80            // bytes per smem row
#define A_ST (128 * ASTRIDE)  // 10240
#define B_ST (64 * ASTRIDE)   // 5120
#define STAGE (A_ST + B_ST)   // 15360

template <int MODE, bool WF32, bool WBF16>
__global__ __launch_bounds__(256)
void tc_gemm(const __nv_bfloat16* __restrict__ A,
             const __nv_bfloat16* __restrict__ W,
             const float* __restrict__ bias,
             float* __restrict__ Cf,
             __nv_bfloat16* __restrict__ Cb,
             int M, int N, int Kc,
             const float* __restrict__ res)
{
    __shared__ __align__(128) uint8_t smem[2 * STAGE];

    const int tid    = threadIdx.x;
    const int warpid = tid >> 5;
    const int lane   = tid & 31;
    const int m0     = blockIdx.y * 128;
    const int n0     = blockIdx.x * 64;

    const int wm = (warpid >> 1) * 32;
    const int wn = (warpid & 1) * 32;

    const uint32_t sbase = smem_u32(smem);

    // cp.async mapping: thread -> (row = tid/4, 16B chunk = tid%4)
    const int r4 = tid >> 2;          // 0..63
    const int c4 = tid & 3;
    const int rowA0 = min(m0 + r4, M - 1);
    const int rowA1 = min(m0 + 64 + r4, M - 1);
    const __nv_bfloat16* Ap0 = A + (size_t)rowA0 * Kc + c4 * 8;
    const __nv_bfloat16* Ap1 = A + (size_t)rowA1 * Kc + c4 * 8;
    const __nv_bfloat16* Bp  = W + (size_t)(n0 + r4) * Kc + c4 * 8;
    const uint32_t dA0 = (uint32_t)(r4 * ASTRIDE + c4 * 16);
    const uint32_t dA1 = (uint32_t)((64 + r4) * ASTRIDE + c4 * 16);
    const uint32_t dB  = (uint32_t)(A_ST + r4 * ASTRIDE + c4 * 16);

    // ldmatrix lane addressing
    const int l8  = lane & 7;
    const int mtx = lane >> 3;
    const uint32_t aoff = (uint32_t)((wm + (mtx & 1) * 8 + l8) * ASTRIDE + (mtx >> 1) * 16);
    const uint32_t boff = (uint32_t)(A_ST + (wn + (mtx >> 1) * 8 + l8) * ASTRIDE + (mtx & 1) * 16);

    float acc[2][4][4];
    #pragma unroll
    for (int i = 0; i < 2; i++)
        #pragma unroll
        for (int j = 0; j < 4; j++)
            #pragma unroll
            for (int q = 0; q < 4; q++) acc[i][j][q] = 0.f;

    const int KT = Kc / 32;

    // prologue: stage 0
    {
        uint32_t b = sbase;
        CP16(b + dA0, Ap0);
        CP16(b + dA1, Ap1);
        CP16(b + dB,  Bp);
        CP_COMMIT();
    }

    for (int kt = 0; kt < KT; kt++) {
        if (kt + 1 < KT) {
            uint32_t b = sbase + ((kt + 1) & 1) * STAGE;
            const int ko = (kt + 1) * 32;
            CP16(b + dA0, Ap0 + ko);
            CP16(b + dA1, Ap1 + ko);
            CP16(b + dB,  Bp  + ko);
            CP_COMMIT();
            CP_WAIT(1);
        } else {
            CP_WAIT(0);
        }
        __syncthreads();

        const uint32_t abase = sbase + (kt & 1) * STAGE + aoff;
        const uint32_t bbase = sbase + (kt & 1) * STAGE + boff;

        #pragma unroll
        for (int ks = 0; ks < 2; ks++) {
            uint32_t a0[4], a1[4], b0[4], b1[4];
            LDSM4(a0[0], a0[1], a0[2], a0[3], abase + ks * 32);
            LDSM4(a1[0], a1[1], a1[2], a1[3], abase + 16 * ASTRIDE + ks * 32);
            LDSM4(b0[0], b0[1], b0[2], b0[3], bbase + ks * 32);
            LDSM4(b1[0], b1[1], b1[2], b1[3], bbase + 16 * ASTRIDE + ks * 32);

            MMA16816(acc[0][0], a0[0], a0[1], a0[2], a0[3], b0[0], b0[1]);
            MMA16816(acc[0][1], a0[0], a0[1], a0[2], a0[3], b0[2], b0[3]);
            MMA16816(acc[0][2], a0[0], a0[1], a0[2], a0[3], b1[0], b1[1]);
            MMA16816(acc[0][3], a0[0], a0[1], a0[2], a0[3], b1[2], b1[3]);
            MMA16816(acc[1][0], a1[0], a1[1], a1[2], a1[3], b0[0], b0[1]);
            MMA16816(acc[1][1], a1[0], a1[1], a1[2], a1[3], b0[2], b0[3]);
            MMA16816(acc[1][2], a1[0], a1[1], a1[2], a1[3], b1[0], b1[1]);
            MMA16816(acc[1][3], a1[0], a1[1], a1[2], a1[3], b1[2], b1[3]);
        }
        __syncthreads();
    }

    // epilogue
    const int r  = lane >> 2;
    const int c2 = (lane & 3) * 2;

    #pragma unroll
    for (int mi = 0; mi < 2; mi++) {
        #pragma unroll
        for (int half = 0; half < 2; half++) {
            const int m = m0 + wm + mi * 16 + r + half * 8;
            if (m >= M) continue;
            const int orow = (MODE == 2) ? patch_to_xs_row(m) : m;
            #pragma unroll
            for (int nj = 0; nj < 4; nj++) {
                const int n = n0 + wn + nj * 8 + c2;
                float v0 = acc[mi][nj][half * 2 + 0] + bias[n];
                float v1 = acc[mi][nj][half * 2 + 1] + bias[n + 1];
                if (MODE == 1) {
                    const float2 rv = *(const float2*)(res + (size_t)m * N + n);
                    v0 = gelu_exact(rv.x + v0);
                    v1 = gelu_exact(rv.y + v1);
                } else if (MODE == 2) {
                    const float2 rv = *(const float2*)(res + (size_t)orow * N + n);
                    v0 += rv.x; v1 += rv.y;
                } else if (MODE == 3) {
                    const float2 rv = *(const float2*)(res + (size_t)m * N + n);
                    v0 += rv.x; v1 += rv.y;
                }
                if (WF32) {
                    float2 o; o.x = v0; o.y = v1;
                    *(float2*)(Cf + (size_t)orow * N + n) = o;
                }
                if (WBF16) {
                    *(uint32_t*)(Cb + (size_t)orow * N + n) = pack_bf2(v0, v1);
                }
            }
        }
    }
}

// ---------------- fp32 -> bf16 conversion ----------------
__global__ void f2b_kernel(const float* __restrict__ s,
                           __nv_bfloat16* __restrict__ d, int n)
{
    int i = (blockIdx.x * blockDim.x + threadIdx.x) * 4;
    if (i + 3 < n) {
        float4 v = *(const float4*)(s + i);
        uint2 o;
        o.x = pack_bf2(v.x, v.y);
        o.y = pack_bf2(v.z, v.w);
        *(uint2*)((uint16_t*)d + i) = o;
    } else {
        for (; i < n; i++) d[i] = __float2bfloat16(s[i]);
    }
}

__global__ void wconv_kernel(const float* s0, const float* s1, const float* s2,
                             const float* s3, const float* s4, const float* s5)
{
    const int stride = gridDim.x * blockDim.x;
    const int t = blockIdx.x * blockDim.x + threadIdx.x;
    for (int i = t; i < DH * D_MOD;   i += stride) g_w_fc1[i]  = __float2bfloat16(s0[i]);
    for (int i = t; i < 64 * DH;      i += stride) g_w_cA[i]   = __float2bfloat16(s1[i]);
    for (int i = t; i < DH * 64;      i += stride) g_w_cB[i]   = __float2bfloat16(s2[i]);
    for (int i = t; i < 3 * DH * DH;  i += stride) g_w_qkv[i]  = __float2bfloat16(s3[i]);
    for (int i = t; i < DH * DH;      i += stride) g_w_proj[i] = __float2bfloat16(s4[i]);
    for (int i = t; i < D_MOD * DH;   i += stride) g_w_fc2[i]  = __float2bfloat16(s5[i]);
}

// ---------------- LayerNorm (fp32 in, bf16 out) ----------------
__global__ void ln_kernel(const float* __restrict__ xs,
                          const float* __restrict__ gamma,
                          const float* __restrict__ beta,
                          __nv_bfloat16* __restrict__ y)
{
    const int pr  = blockIdx.x;
    const int tid = threadIdx.x;
    const int row = patch_to_xs_row(pr);

    float v = xs[(size_t)row * DH + tid];

    __shared__ float red[40];

    float s = v;
    #pragma unroll
    for (int off = 16; off > 0; off >>= 1) s += __shfl_down_sync(0xffffffff, s, off);
    if ((tid & 31) == 0) red[tid >> 5] = s;
    __syncthreads();
    if (tid == 0) {
        float tot = 0.f;
        #pragma unroll
        for (int i = 0; i < 6; i++) tot += red[i];
        red[32] = tot * (1.0f / DH);
    }
    __syncthreads();
    float mu = red[32];

    float d  = v - mu;
    float s2 = d * d;
    #pragma unroll
    for (int off = 16; off > 0; off >>= 1) s2 += __shfl_down_sync(0xffffffff, s2, off);
    if ((tid & 31) == 0) red[8 + (tid >> 5)] = s2;
    __syncthreads();
    if (tid == 0) {
        float tot = 0.f;
        #pragma unroll
        for (int i = 0; i < 6; i++) tot += red[8 + i];
        red[33] = rsqrtf(tot * (1.0f / DH) + 1e-5f);
    }
    __syncthreads();

    y[(size_t)pr * DH + tid] = __float2bfloat16(d * red[33] * gamma[tid] + beta[tid]);
}

// ---------------- 3D neighborhood attention (fp32 in, bf16 out) ----------------
#define KROW 193

__global__ void attn_kernel(const float* __restrict__ qkv,
                            const float* __restrict__ rpb,
                            __nv_bfloat16* __restrict__ att)
{
    const int pr  = blockIdx.x;
    const int tid = threadIdx.x;
    const int b = pr >> 11;
    const int t = (pr >> 8) & 7;
    const int h = (pr >> 4) & 15;
    const int w = pr & 15;

    __shared__ float s_k[KCUBE * KROW];
    __shared__ float s_q[DH];
    __shared__ int   s_nbr[KCUBE];
    __shared__ float s_sc[HEADS * KCUBE];
    __shared__ float s_p [HEADS * KCUBE];

    const float scale = 0.144337567297406f;   // 48^-0.5
    s_q[tid] = qkv[(size_t)pr * (3 * DH) + tid] * scale;

    const int st = min(max(t - 1, 0), T_FR - 3);
    const int sh = min(max(h - 1, 0), HW - 3);
    const int sw = min(max(w - 1, 0), HW - 3);

    if (tid < KCUBE) {
        int kt = tid / 9, kh = (tid / 3) % 3, kw = tid % 3;
        s_nbr[tid] = (((b * T_FR + st + kt) * HW) + sh + kh) * HW + sw + kw;
    }
    __syncthreads();

    #pragma unroll 4
    for (int nb = 0; nb < KCUBE; nb++)
        s_k[nb * KROW + tid] = qkv[(size_t)s_nbr[nb] * (3 * DH) + DH + tid];
    __syncthreads();

    if (tid < HEADS * KCUBE) {
        int head = tid / KCUBE, nb = tid % KCUBE;
        const float* kp = s_k + nb * KROW + head * HDIM;
        const float* qp = s_q + head * HDIM;
        float s = 0.f;
        #pragma unroll
        for (int j = 0; j < HDIM; j++) s = fmaf(qp[j], kp[j], s);
        int kt = nb / 9, kh = (nb / 3) % 3, kw = nb % 3;
        int rt = st + kt - t + 2;
        int rh = sh + kh - h + 2;
        int rw = sw + kw - w + 2;
        s += rpb[((head * 5 + rt) * 5 + rh) * 5 + rw];
        s_sc[tid] = s;
    }
    __syncthreads();

    if (tid < HEADS) {
        float mx = -1e30f;
        #pragma unroll
        for (int i = 0; i < KCUBE; i++) mx = fmaxf(mx, s_sc[tid * KCUBE + i]);
        float sum = 0.f;
        #pragma unroll
        for (int i = 0; i < KCUBE; i++) {
            float e = __expf(s_sc[tid * KCUBE + i] - mx);
            s_p[tid * KCUBE + i] = e;
            sum += e;
        }
        float inv = 1.0f / sum;
        #pragma unroll
        for (int i = 0; i < KCUBE; i++) s_p[tid * KCUBE + i] *= inv;
    }
    __syncthreads();

    {
        int head = tid / HDIM;
        float o = 0.f;
        #pragma unroll
        for (int nb = 0; nb < KCUBE; nb++)
            o = fmaf(s_p[head * KCUBE + nb],
                     qkv[(size_t)s_nbr[nb] * (3 * DH) + 2 * DH + tid], o);
        att[(size_t)pr * DH + tid] = __float2bfloat16(o);
    }
}

// ---------------- launch ----------------
extern "C" void kernel_launch(void* const* d_in, const int* in_sizes, int n_in,
                              void* d_out, int out_size)
{
    const float* x       = (const float*)d_in[0];
    const float* fc1_w   = (const float*)d_in[1];
    const float* fc1_b   = (const float*)d_in[2];
    const float* convA_w = (const float*)d_in[3];
    const float* convA_b = (const float*)d_in[4];
    const float* convB_w = (const float*)d_in[5];
    const float* convB_b = (const float*)d_in[6];
    const float* ln_g    = (const float*)d_in[7];
    const float* ln_b    = (const float*)d_in[8];
    const float* qkv_w   = (const float*)d_in[9];
    const float* qkv_b   = (const float*)d_in[10];
    const float* rpb     = (const float*)d_in[11];
    const float* proj_w  = (const float*)d_in[12];
    const float* proj_b  = (const float*)d_in[13];
    const float* fc2_w   = (const float*)d_in[14];
    const float* fc2_b   = (const float*)d_in[15];
    float* out = (float*)d_out;

    float *t1, *xs, *qkv;
    __nv_bfloat16 *xb, *t1b, *t2b, *xsb, *yb, *attb;
    __nv_bfloat16 *wfc1, *wcA, *wcB, *wqkv, *wproj, *wfc2;
    cudaGetSymbolAddress((void**)&t1,  g_t1);
    cudaGetSymbolAddress((void**)&xs,  g_xs);
    cudaGetSymbolAddress((void**)&qkv, g_qkv);
    cudaGetSymbolAddress((void**)&xb,   g_xb);
    cudaGetSymbolAddress((void**)&t1b,  g_t1b);
    cudaGetSymbolAddress((void**)&t2b,  g_t2b);
    cudaGetSymbolAddress((void**)&xsb,  g_xsb);
    cudaGetSymbolAddress((void**)&yb,   g_yb);
    cudaGetSymbolAddress((void**)&attb, g_attb);
    cudaGetSymbolAddress((void**)&wfc1,  g_w_fc1);
    cudaGetSymbolAddress((void**)&wcA,   g_w_cA);
    cudaGetSymbolAddress((void**)&wcB,   g_w_cB);
    cudaGetSymbolAddress((void**)&wqkv,  g_w_qkv);
    cudaGetSymbolAddress((void**)&wproj, g_w_proj);
    cudaGetSymbolAddress((void**)&wfc2,  g_w_fc2);

    const int gyA = (M_ALL + 127) / 128;   // 129
    const int gyP = M_PAT / 128;           // 128

    // 0) conversions
    {
        const int n = M_ALL * D_MOD;
        f2b_kernel<<<(n / 4 + 255) / 256, 256>>>(x, xb, n);
        wconv_kernel<<<114, 256>>>(fc1_w, convA_w, convB_w, qkv_w, proj_w, fc2_w);
    }
    // 1) fc1 -> t1 (f32) + t1b (bf16)
    tc_gemm<0, true, true><<<dim3(3, gyA), 256>>>(xb, wfc1, fc1_b, t1, t1b,
                                                  M_ALL, DH, D_MOD, nullptr);
    // 2) convA -> t2b (bf16)
    tc_gemm<0, false, true><<<dim3(1, gyA), 256>>>(t1b, wcA, convA_b, nullptr, t2b,
                                                   M_ALL, 64, DH, nullptr);
    // 3) convB + residual(t1) + gelu -> xs (f32) + xsb (bf16)
    tc_gemm<1, true, true><<<dim3(3, gyA), 256>>>(t2b, wcB, convB_b, xs, xsb,
                                                  M_ALL, DH, 64, t1);
    // 4) LayerNorm -> yb (bf16)
    ln_kernel<<<M_PAT, DH>>>(xs, ln_g, ln_b, yb);
    // 5) qkv -> qkv (f32)
    tc_gemm<0, true, false><<<dim3(9, gyP), 256>>>(yb, wqkv, qkv_b, qkv, nullptr,
                                                   M_PAT, 3 * DH, DH, nullptr);
    // 6) attention -> attb (bf16)
    attn_kernel<<<M_PAT, DH>>>(qkv, rpb, attb);
    // 7) proj: xsb[rr] = xs[rr] + proj(attb) + b   (bf16 out only)
    tc_gemm<2, false, true><<<dim3(3, gyP), 256>>>(attb, wproj, proj_b, nullptr, xsb,
                                                   M_PAT, DH, DH, xs);
    // 8) fc2 + outer residual(x) -> out (f32)
    tc_gemm<3, true, false><<<dim3(12, gyA), 256>>>(xsb, wfc2, fc2_b, out, nullptr,
                                                    M_ALL, D_MOD, DH, x);
}